// round 10
// baseline (speedup 1.0000x reference)
#include <cuda_runtime.h>
#include <math.h>
#include <stdint.h>

#define NN 100000
#define NE 600000
#define NG 256

// ---------------- scratch layout (floats) ----------------
static constexpr size_t OFF_TX    = 0;                         // [NN,640] Chebyshev slices
static constexpr size_t OFF_H1    = OFF_TX + (size_t)NN*640;   // [NN,128]
static constexpr size_t OFF_H2    = OFF_H1 + (size_t)NN*128;   // [NN,512]
static constexpr size_t OFF_DEGA  = OFF_H2 + (size_t)NN*512;   // deg over src
static constexpr size_t OFF_DEGB  = OFF_DEGA + NN;             // deg over dst
static constexpr size_t OFF_DINVA = OFF_DEGB + NN;
static constexpr size_t OFF_DINVB = OFF_DINVA + NN;
static constexpr size_t OFF_POOL  = OFF_DINVB + NN;            // [NG,512]
static constexpr size_t OFF_CNT   = OFF_POOL + (size_t)NG*512; // [NG]
static constexpr size_t OFF_WT    = OFF_CNT + NG;              // bf16x2-packed weights [256*320 u32]
static constexpr size_t BUF_TOTAL = OFF_WT + (size_t)256*320;

__device__ float g_buf[BUF_TOTAL];

// packed edge records: {gather_idx, weight_bits}; fwd at [0,NE), rev at [NE,2NE)
__device__ int2 g_ev[2 * NE];

// ---------------- int scratch ----------------
static constexpr int IB_ROWF = 0;
static constexpr int IB_ROWR = NN;
static constexpr int IB_CURF = 2*NN;   // after scatter: row end
static constexpr int IB_CURR = 3*NN;
static constexpr int IB_BSF  = 4*NN;
static constexpr int IB_BSR  = IB_BSF + 128;
static constexpr int IB_TOTAL= IB_BSR + 128;

__device__ int g_ib[IB_TOTAL];

static constexpr int NB = (NN + 1023) / 1024;

// ============================================================
// helpers
// ============================================================
__device__ __forceinline__ uint32_t pack_bf16(float lo, float hi) {
    uint32_t u;
    asm("cvt.rn.bf16x2.f32 %0, %1, %2;" : "=r"(u) : "f"(hi), "f"(lo));
    return u;
}

__device__ __forceinline__ void mma16816(float* d, const uint32_t* a, const uint32_t* b) {
    asm volatile(
        "mma.sync.aligned.m16n8k16.row.col.f32.bf16.bf16.f32 "
        "{%0,%1,%2,%3}, {%4,%5,%6,%7}, {%8,%9}, {%0,%1,%2,%3};"
        : "+f"(d[0]), "+f"(d[1]), "+f"(d[2]), "+f"(d[3])
        : "r"(a[0]), "r"(a[1]), "r"(a[2]), "r"(a[3]), "r"(b[0]), "r"(b[1]));
}

// ============================================================
// small utility kernels
// ============================================================
__global__ void k_zero(size_t off, int n) {
    int i = blockIdx.x * blockDim.x + threadIdx.x;
    if (i < n) g_buf[off + i] = 0.0f;
}

__global__ void k_deg(const int* __restrict__ src, const int* __restrict__ dst) {
    int e = blockIdx.x * blockDim.x + threadIdx.x;
    if (e >= NE) return;
    atomicAdd(&g_buf[OFF_DEGA + src[e]], 1.0f);
    atomicAdd(&g_buf[OFF_DEGB + dst[e]], 1.0f);
}

__global__ void k_dinv() {
    int n = blockIdx.x * blockDim.x + threadIdx.x;
    if (n >= NN) return;
    float a = g_buf[OFF_DEGA + n];
    float b = g_buf[OFF_DEGB + n];
    g_buf[OFF_DINVA + n] = (a > 0.0f) ? rsqrtf(a) : 0.0f;
    g_buf[OFF_DINVB + n] = (b > 0.0f) ? rsqrtf(b) : 0.0f;
}

// ============================================================
// CSR build: block sums -> scan -> row starts -> scatter
// ============================================================
__global__ void k_blocksum() {
    int tid  = threadIdx.x;
    int i    = blockIdx.x * 1024 + tid;
    int lane = tid & 31, wid = tid >> 5;
    int dF = (i < NN) ? (int)g_buf[OFF_DEGB + i] : 0;
    int dR = (i < NN) ? (int)g_buf[OFF_DEGA + i] : 0;
    #pragma unroll
    for (int o = 16; o > 0; o >>= 1) {
        dF += __shfl_down_sync(0xffffffffu, dF, o);
        dR += __shfl_down_sync(0xffffffffu, dR, o);
    }
    __shared__ int sF[32], sR[32];
    if (lane == 0) { sF[wid] = dF; sR[wid] = dR; }
    __syncthreads();
    if (wid == 0) {
        int vF = sF[lane], vR = sR[lane];
        #pragma unroll
        for (int o = 16; o > 0; o >>= 1) {
            vF += __shfl_down_sync(0xffffffffu, vF, o);
            vR += __shfl_down_sync(0xffffffffu, vR, o);
        }
        if (lane == 0) { g_ib[IB_BSF + blockIdx.x] = vF; g_ib[IB_BSR + blockIdx.x] = vR; }
    }
}

__global__ void k_scanblocks() {
    __shared__ int sF[128], sR[128];
    int tid = threadIdx.x;
    int vF = (tid < NB) ? g_ib[IB_BSF + tid] : 0;
    int vR = (tid < NB) ? g_ib[IB_BSR + tid] : 0;
    sF[tid] = vF; sR[tid] = vR;
    __syncthreads();
    for (int s = 1; s < 128; s <<= 1) {
        int aF = (tid >= s) ? sF[tid - s] : 0;
        int aR = (tid >= s) ? sR[tid - s] : 0;
        __syncthreads();
        sF[tid] += aF; sR[tid] += aR;
        __syncthreads();
    }
    if (tid < NB) {
        g_ib[IB_BSF + tid] = sF[tid] - vF;
        g_ib[IB_BSR + tid] = sR[tid] - vR;
    }
}

__global__ void k_writerow() {
    int tid = threadIdx.x;
    int i   = blockIdx.x * 1024 + tid;
    int lane = tid & 31, wid = tid >> 5;
    int dF = (i < NN) ? (int)g_buf[OFF_DEGB + i] : 0;
    int dR = (i < NN) ? (int)g_buf[OFF_DEGA + i] : 0;
    int iF = dF, iR = dR;
    #pragma unroll
    for (int o = 1; o < 32; o <<= 1) {
        int tF = __shfl_up_sync(0xffffffffu, iF, o);
        int tR = __shfl_up_sync(0xffffffffu, iR, o);
        if (lane >= o) { iF += tF; iR += tR; }
    }
    __shared__ int wsF[32], wsR[32];
    if (lane == 31) { wsF[wid] = iF; wsR[wid] = iR; }
    __syncthreads();
    if (wid == 0) {
        int vF = wsF[lane], vR = wsR[lane];
        int jF = vF, jR = vR;
        #pragma unroll
        for (int o = 1; o < 32; o <<= 1) {
            int tF = __shfl_up_sync(0xffffffffu, jF, o);
            int tR = __shfl_up_sync(0xffffffffu, jR, o);
            if (lane >= o) { jF += tF; jR += tR; }
        }
        wsF[lane] = jF - vF;
        wsR[lane] = jR - vR;
    }
    __syncthreads();
    int exF = (iF - dF) + wsF[wid] + g_ib[IB_BSF + blockIdx.x];
    int exR = (iR - dR) + wsR[wid] + g_ib[IB_BSR + blockIdx.x];
    if (i < NN) {
        g_ib[IB_ROWF + i] = exF; g_ib[IB_CURF + i] = exF;
        g_ib[IB_ROWR + i] = exR; g_ib[IB_CURR + i] = exR;
    }
}

__global__ void k_scatter(const int* __restrict__ src, const int* __restrict__ dst) {
    int e = blockIdx.x * blockDim.x + threadIdx.x;
    if (e >= NE) return;
    int s = src[e], d = dst[e];
    float dAs = g_buf[OFF_DINVA + s], dAd = g_buf[OFF_DINVA + d];
    float dBs = g_buf[OFF_DINVB + s], dBd = g_buf[OFF_DINVB + d];
    float wf = -dAs * dAd;
    float wr = -dBd * dBs;
    int pF = atomicAdd(&g_ib[IB_CURF + d], 1);
    g_ev[pF] = make_int2(s, __float_as_int(wf));
    int pR = atomicAdd(&g_ib[IB_CURR + s], 1);
    g_ev[NE + pR] = make_int2(d, __float_as_int(wr));
}

// ============================================================
// copy Tx0 slice into TxAll[:,0:F]
// ============================================================
template<int F>
__global__ void col_copy(size_t dstOff, int dstLd, int mode,
                         const float* __restrict__ ext, size_t srcOff, int srcLd) {
    constexpr int P = F / 4;
    int t = blockIdx.x * blockDim.x + threadIdx.x;
    if (t >= NN * P) return;
    int n = t / P;
    int j = (t % P) * 4;
    float4 v;
    if (mode == 1) v = *(const float4*)(ext + (size_t)n * srcLd + j);
    else           v = *(const float4*)&g_buf[srcOff + (size_t)n * srcLd + j];
    *(float4*)&g_buf[dstOff + (size_t)n * dstLd + j] = v;
}

// ============================================================
// gather CSR SpMM over a W-column slice, fused Chebyshev recursion.
// Edge loop unrolled x4 with dual accumulators -> 4 independent gathers in
// flight per thread (latency hiding). Gather source may be an external
// array (mode 1) or g_buf (mode 0) with its own leading dim.
// ============================================================
template<int W>
__global__ void spmm_w(int inMode, const float* __restrict__ extIn,
                       size_t inOff, int inLd,
                       size_t outOff, size_t prevOff, int hasPrev, int outLd,
                       int rowBase, int curBase, int evBase) {
    constexpr int LPN = W / 4;
    int gtid = blockIdx.x * blockDim.x + threadIdx.x;
    int node = gtid / LPN;
    if (node >= NN) return;
    int sub = gtid % LPN;
    int start = g_ib[rowBase + node];
    int end   = g_ib[curBase + node];

    const float* inB = (inMode == 1) ? (extIn + sub * 4)
                                     : (g_buf + inOff + sub * 4);
    float4 a0 = make_float4(0.f, 0.f, 0.f, 0.f);
    float4 a1 = make_float4(0.f, 0.f, 0.f, 0.f);

    const int2* evp = g_ev + evBase;
    int e = start;
    for (; e + 4 <= end; e += 4) {
        int2 e0 = evp[e], e1 = evp[e + 1], e2 = evp[e + 2], e3 = evp[e + 3];
        const float4 v0 = *(const float4*)(inB + (size_t)e0.x * inLd);
        const float4 v1 = *(const float4*)(inB + (size_t)e1.x * inLd);
        const float4 v2 = *(const float4*)(inB + (size_t)e2.x * inLd);
        const float4 v3 = *(const float4*)(inB + (size_t)e3.x * inLd);
        float w0 = __int_as_float(e0.y), w1 = __int_as_float(e1.y);
        float w2 = __int_as_float(e2.y), w3 = __int_as_float(e3.y);
        a0.x = fmaf(w0, v0.x, a0.x); a1.x = fmaf(w1, v1.x, a1.x);
        a0.y = fmaf(w0, v0.y, a0.y); a1.y = fmaf(w1, v1.y, a1.y);
        a0.z = fmaf(w0, v0.z, a0.z); a1.z = fmaf(w1, v1.z, a1.z);
        a0.w = fmaf(w0, v0.w, a0.w); a1.w = fmaf(w1, v1.w, a1.w);
        a0.x = fmaf(w2, v2.x, a0.x); a1.x = fmaf(w3, v3.x, a1.x);
        a0.y = fmaf(w2, v2.y, a0.y); a1.y = fmaf(w3, v3.y, a1.y);
        a0.z = fmaf(w2, v2.z, a0.z); a1.z = fmaf(w3, v3.z, a1.z);
        a0.w = fmaf(w2, v2.w, a0.w); a1.w = fmaf(w3, v3.w, a1.w);
    }
    if (e + 2 <= end) {
        int2 e0 = evp[e], e1 = evp[e + 1];
        const float4 v0 = *(const float4*)(inB + (size_t)e0.x * inLd);
        const float4 v1 = *(const float4*)(inB + (size_t)e1.x * inLd);
        float w0 = __int_as_float(e0.y), w1 = __int_as_float(e1.y);
        a0.x = fmaf(w0, v0.x, a0.x); a1.x = fmaf(w1, v1.x, a1.x);
        a0.y = fmaf(w0, v0.y, a0.y); a1.y = fmaf(w1, v1.y, a1.y);
        a0.z = fmaf(w0, v0.z, a0.z); a1.z = fmaf(w1, v1.z, a1.z);
        a0.w = fmaf(w0, v0.w, a0.w); a1.w = fmaf(w1, v1.w, a1.w);
        e += 2;
    }
    if (e < end) {
        int2 e0 = evp[e];
        const float4 v0 = *(const float4*)(inB + (size_t)e0.x * inLd);
        float w0 = __int_as_float(e0.y);
        a0.x = fmaf(w0, v0.x, a0.x);
        a0.y = fmaf(w0, v0.y, a0.y);
        a0.z = fmaf(w0, v0.z, a0.z);
        a0.w = fmaf(w0, v0.w, a0.w);
    }
    float ax = a0.x + a1.x, ay = a0.y + a1.y, az = a0.z + a1.z, aw = a0.w + a1.w;

    float4 r;
    if (hasPrev) {
        const float4 p = *(const float4*)&g_buf[prevOff + (size_t)node * outLd + sub * 4];
        r.x = 2.f * ax - p.x; r.y = 2.f * ay - p.y;
        r.z = 2.f * az - p.z; r.w = 2.f * aw - p.w;
    } else {
        r.x = ax; r.y = ay; r.z = az; r.w = aw;
    }
    *(float4*)&g_buf[outOff + (size_t)node * outLd + sub * 4] = r;
}

// ============================================================
// weight transpose + bf16x2 pack
// ============================================================
__global__ void k_transb(const float* __restrict__ W, int Kdim, int FOUT) {
    int K2 = Kdim / 2;
    int t = blockIdx.x * blockDim.x + threadIdx.x;
    if (t >= FOUT * K2) return;
    int n = t / K2, k2 = t % K2;
    float lo = W[(size_t)(2 * k2) * FOUT + n];
    float hi = W[(size_t)(2 * k2 + 1) * FOUT + n];
    g_buf[OFF_WT + t] = __uint_as_float(pack_bf16(lo, hi));
}

// ============================================================
// bf16 mma.sync GEMM: C[:, hc0 + n0 : +BN] = relu(A[NN,Kdim] @ WT^T + bias)
// ============================================================
template<int BN, int BK>
__global__ void __launch_bounds__(256)
gemm_bf16(size_t aOff, int lda, int Kdim,
          const float* __restrict__ bias, size_t cOff, int ldc, int hc0) {
    constexpr int BM = 128;
    constexpr int PW = BK / 2 + 4;
    constexpr int KS = BK / 16;
    constexpr int NT = BN / 32;
    constexpr int ASZ = BM * PW;
    constexpr int BSZ = BN * PW;
    constexpr int AOCT = BM * BK / 8;
    constexpr int AO_PER = (AOCT + 255) / 256;
    constexpr int BQ  = BN * BK / 8;
    constexpr int BO_PER = (BQ + 255) / 256;
    constexpr int OPR = BK / 8;

    __shared__ uint32_t sm[2 * ASZ + 2 * BSZ];
    uint32_t* As[2] = { sm, sm + ASZ };
    uint32_t* Bs[2] = { sm + 2 * ASZ, sm + 2 * ASZ + BSZ };

    int tid  = threadIdx.x;
    int wid  = tid >> 5;
    int lane = tid & 31;
    int wm   = wid >> 2;
    int wn   = wid & 3;
    int m0   = blockIdx.x * BM;
    int n0   = blockIdx.y * BN;
    int l4   = lane >> 2;
    int lq   = lane & 3;
    const int K2 = Kdim / 2;
    const uint32_t* WTu = (const uint32_t*)&g_buf[OFF_WT];

    float acc[4][NT][4];
    #pragma unroll
    for (int mt = 0; mt < 4; mt++)
        #pragma unroll
        for (int nt = 0; nt < NT; nt++)
            #pragma unroll
            for (int q = 0; q < 4; q++) acc[mt][nt][q] = 0.f;

    const int NC = Kdim / BK;

    float4 ra[AO_PER][2];
    uint4  rb[BO_PER];

    auto ldg = [&](int kc) {
        int k0 = kc * BK;
        #pragma unroll
        for (int i = 0; i < AO_PER; i++) {
            int id = tid + i * 256;
            int r = id / OPR, o = id % OPR;
            int gr = m0 + r;
            if (gr < NN) {
                ra[i][0] = *(const float4*)&g_buf[aOff + (size_t)gr * lda + k0 + o * 8];
                ra[i][1] = *(const float4*)&g_buf[aOff + (size_t)gr * lda + k0 + o * 8 + 4];
            } else {
                ra[i][0] = make_float4(0.f, 0.f, 0.f, 0.f);
                ra[i][1] = make_float4(0.f, 0.f, 0.f, 0.f);
            }
        }
        #pragma unroll
        for (int i = 0; i < BO_PER; i++) {
            int id = tid + i * 256;
            if ((BQ & 255) == 0 || id < BQ) {
                int r = id / OPR, q = id % OPR;
                rb[i] = *(const uint4*)&WTu[(size_t)(n0 + r) * K2 + kc * (BK / 2) + q * 4];
            }
        }
    };

    auto sts = [&](int st) {
        #pragma unroll
        for (int i = 0; i < AO_PER; i++) {
            int id = tid + i * 256;
            int r = id / OPR, o = id % OPR;
            uint4 u;
            u.x = pack_bf16(ra[i][0].x, ra[i][0].y);
            u.y = pack_bf16(ra[i][0].z, ra[i][0].w);
            u.z = pack_bf16(ra[i][1].x, ra[i][1].y);
            u.w = pack_bf16(ra[i][1].z, ra[i][1].w);
            *(uint4*)&As[st][r * PW + o * 4] = u;
        }
        #pragma unroll
        for (int i = 0; i < BO_PER; i++) {
            int id = tid + i * 256;
            if ((BQ & 255) == 0 || id < BQ) {
                int r = id / OPR, q = id % OPR;
                *(uint4*)&Bs[st][r * PW + q * 4] = rb[i];
            }
        }
    };

    auto compute = [&](int st) {
        const uint32_t* aB = As[st] + (wm * 64 + l4) * PW + lq;
        const uint32_t* bB = Bs[st] + (wn * (BN / 4) + l4) * PW + lq;
        #pragma unroll
        for (int ks = 0; ks < KS; ks++) {
            uint32_t af[4][4];
            #pragma unroll
            for (int mt = 0; mt < 4; mt++) {
                const uint32_t* p = aB + mt * 16 * PW + ks * 8;
                af[mt][0] = p[0];
                af[mt][1] = p[8 * PW];
                af[mt][2] = p[4];
                af[mt][3] = p[8 * PW + 4];
            }
            uint32_t bf[NT][2];
            #pragma unroll
            for (int nt = 0; nt < NT; nt++) {
                const uint32_t* q = bB + nt * 8 * PW + ks * 8;
                bf[nt][0] = q[0];
                bf[nt][1] = q[4];
            }
            #pragma unroll
            for (int mt = 0; mt < 4; mt++)
                #pragma unroll
                for (int nt = 0; nt < NT; nt++)
                    mma16816(acc[mt][nt], af[mt], bf[nt]);
        }
    };

    ldg(0);
    sts(0);
    __syncthreads();

    for (int c = 0; c < NC; c++) {
        int st = c & 1;
        bool has = (c + 1 < NC);
        if (has) ldg(c + 1);
        compute(st);
        if (has) sts(st ^ 1);
        __syncthreads();
    }

    #pragma unroll
    for (int mt = 0; mt < 4; mt++) {
        int row = m0 + wm * 64 + mt * 16 + l4;
        #pragma unroll
        for (int nt = 0; nt < NT; nt++) {
            int col = n0 + wn * (BN / 4) + nt * 8 + 2 * lq;
            float b0 = bias[col], b1 = bias[col + 1];
            if (row < NN) {
                float2 o0;
                o0.x = fmaxf(acc[mt][nt][0] + b0, 0.f);
                o0.y = fmaxf(acc[mt][nt][1] + b1, 0.f);
                *(float2*)&g_buf[cOff + (size_t)row * ldc + hc0 + col] = o0;
            }
            if (row + 8 < NN) {
                float2 o1;
                o1.x = fmaxf(acc[mt][nt][2] + b0, 0.f);
                o1.y = fmaxf(acc[mt][nt][3] + b1, 0.f);
                *(float2*)&g_buf[cOff + (size_t)(row + 8) * ldc + hc0 + col] = o1;
            }
        }
    }
}

// ============================================================
// pooling + head
// ============================================================
__global__ void k_cnt(const int* __restrict__ batch) {
    int i = blockIdx.x * blockDim.x + threadIdx.x;
    if (i >= NN) return;
    atomicAdd(&g_buf[OFF_CNT + batch[i]], 1.0f);
}

__global__ void pool_kernel(const int* __restrict__ batch) {
    constexpr int NPB = 512;
    __shared__ int sb[NPB];
    int n0  = blockIdx.x * NPB;
    int tid = threadIdx.x;
    int nmax = NN - n0; if (nmax > NPB) nmax = NPB;
    if (tid < nmax) sb[tid] = batch[n0 + tid];
    __syncthreads();
    int f = tid;
    float acc = 0.f;
    int cur = sb[0];
    for (int i = 0; i < nmax; i++) {
        int b = sb[i];
        if (b != cur) {
            atomicAdd(&g_buf[OFF_POOL + (size_t)cur * 512 + f], acc);
            acc = 0.f; cur = b;
        }
        acc += g_buf[OFF_H2 + (size_t)(n0 + i) * 512 + f];
    }
    atomicAdd(&g_buf[OFF_POOL + (size_t)cur * 512 + f], acc);
}

__global__ void head_kernel(const float* __restrict__ fcw, const float* __restrict__ fcb,
                            float* __restrict__ out) {
    int g = blockIdx.x;
    int tid = threadIdx.x;
    __shared__ float red[128][4];
    float acc[4] = {0.f, 0.f, 0.f, 0.f};
    for (int j = tid; j < 512; j += 128) {
        float p = g_buf[OFF_POOL + (size_t)g * 512 + j];
        #pragma unroll
        for (int c = 0; c < 4; c++) acc[c] = fmaf(p, fcw[j * 4 + c], acc[c]);
    }
    #pragma unroll
    for (int c = 0; c < 4; c++) red[tid][c] = acc[c];
    __syncthreads();
    for (int s = 64; s > 0; s >>= 1) {
        if (tid < s) {
            #pragma unroll
            for (int c = 0; c < 4; c++) red[tid][c] += red[tid + s][c];
        }
        __syncthreads();
    }
    if (tid == 0) {
        float ic = 1.0f / fmaxf(g_buf[OFF_CNT + g], 1.0f);
        float l[4];
        #pragma unroll
        for (int c = 0; c < 4; c++) l[c] = red[0][c] * ic + fcb[c];
        float m = fmaxf(fmaxf(l[0], l[1]), fmaxf(l[2], l[3]));
        float s = 0.f;
        #pragma unroll
        for (int c = 0; c < 4; c++) s += expf(l[c] - m);
        float ls = logf(s);
        #pragma unroll
        for (int c = 0; c < 4; c++) out[g * 4 + c] = l[c] - m - ls;
    }
}

// ============================================================
// host-side conv driver
// ============================================================
static inline int cdiv_ll(long long a, int b) { return (int)((a + b - 1) / b); }

template<int F, int FOUT>
static void run_conv(const float* extX, size_t xOff, int xLd, int xmode,
                     int rowBase, int curBase, int evBase,
                     const float* Wstack, const float* bias,
                     size_t hOff, int hLd, int hc0) {
    constexpr int LD = 5 * F;
    constexpr int W  = (F >= 64) ? 64 : F;       // slice width per SpMM chain
    constexpr int NH = F / W;                    // halves
    constexpr int LPN = W / 4;
    int ccGrid = cdiv_ll((long long)NN * (F / 4), 256);
    int spGrid = cdiv_ll((long long)NN * LPN, 256);

    col_copy<F><<<ccGrid, 256>>>(OFF_TX, LD, xmode, extX, xOff, xLd);
    // per-half Chebyshev chains; T1 gathers straight from the compact source
    for (int h = 0; h < NH; h++) {
        size_t hb = (size_t)h * W;
        spmm_w<W><<<spGrid, 256>>>(xmode, extX, xOff + hb, xLd,
                                   OFF_TX + F + hb, 0, 0, LD,
                                   rowBase, curBase, evBase);
        for (int k = 2; k < 5; k++) {
            spmm_w<W><<<spGrid, 256>>>(0, nullptr,
                                       OFF_TX + (size_t)(k - 1) * F + hb, LD,
                                       OFF_TX + (size_t)k * F + hb,
                                       OFF_TX + (size_t)(k - 2) * F + hb, 1, LD,
                                       rowBase, curBase, evBase);
        }
    }
    k_transb<<<cdiv_ll(FOUT * (LD / 2), 256), 256>>>(Wstack, LD, FOUT);
    if constexpr (FOUT == 64) {
        dim3 grid((NN + 127) / 128, 1);
        gemm_bf16<64, 16><<<grid, 256>>>(OFF_TX, LD, LD, bias, hOff, hLd, hc0);
    } else {
        dim3 grid((NN + 127) / 128, FOUT / 128);
        gemm_bf16<128, 32><<<grid, 256>>>(OFF_TX, LD, LD, bias, hOff, hLd, hc0);
    }
}

extern "C" void kernel_launch(void* const* d_in, const int* in_sizes, int n_in,
                              void* d_out, int out_size) {
    const float* x     = (const float*)d_in[0];
    const int*   ei    = (const int*)d_in[1];
    const int*   batch = (const int*)d_in[2];
    const float* W11   = (const float*)d_in[3];
    const float* b11   = (const float*)d_in[4];
    const float* W12   = (const float*)d_in[5];
    const float* b12   = (const float*)d_in[6];
    const float* W21   = (const float*)d_in[7];
    const float* b21   = (const float*)d_in[8];
    const float* W22   = (const float*)d_in[9];
    const float* b22   = (const float*)d_in[10];
    const float* fcw   = (const float*)d_in[11];
    const float* fcb   = (const float*)d_in[12];
    float* out = (float*)d_out;

    const int* src = ei;
    const int* dst = ei + NE;

    k_zero<<<cdiv_ll(2 * NN, 256), 256>>>(OFF_DEGA, 2 * NN);
    k_zero<<<cdiv_ll(NG * 512 + NG, 256), 256>>>(OFF_POOL, NG * 512 + NG);

    k_deg<<<cdiv_ll(NE, 256), 256>>>(src, dst);
    k_dinv<<<cdiv_ll(NN, 256), 256>>>();

    k_blocksum<<<NB, 1024>>>();
    k_scanblocks<<<1, 128>>>();
    k_writerow<<<NB, 1024>>>();
    k_scatter<<<cdiv_ll(NE, 256), 256>>>(src, dst);

    run_conv<16, 64>(x, 0, 16, 1, IB_ROWF, IB_CURF, 0,
                     W11, b11, OFF_H1, 128, 0);
    run_conv<16, 64>(x, 0, 16, 1, IB_ROWR, IB_CURR, NE,
                     W12, b12, OFF_H1, 128, 64);

    const float* h1ptr = nullptr;   // layer 2 gathers H1 via g_buf offset (mode 0)
    run_conv<128, 256>(h1ptr, OFF_H1, 128, 0, IB_ROWF, IB_CURF, 0,
                       W21, b21, OFF_H2, 512, 0);
    run_conv<128, 256>(h1ptr, OFF_H1, 128, 0, IB_ROWR, IB_CURR, NE,
                       W22, b22, OFF_H2, 512, 256);

    k_cnt<<<cdiv_ll(NN, 256), 256>>>(batch);
    pool_kernel<<<(NN + 511) / 512, 512>>>(batch);
    head_kernel<<<NG, 128>>>(fcw, fcb, out);
}

// round 11
// speedup vs baseline: 1.3731x; 1.3731x over previous
#include <cuda_runtime.h>
#include <math.h>
#include <stdint.h>

#define NN 100000
#define NE 600000
#define NG 256

// ---------------- scratch layout (floats) ----------------
static constexpr size_t OFF_TX    = 0;                         // [NN,640] Chebyshev slices
static constexpr size_t OFF_H1    = OFF_TX + (size_t)NN*640;   // [NN,128]
static constexpr size_t OFF_H2    = OFF_H1 + (size_t)NN*128;   // [NN,512]
static constexpr size_t OFF_DEGA  = OFF_H2 + (size_t)NN*512;   // deg over src
static constexpr size_t OFF_DEGB  = OFF_DEGA + NN;             // deg over dst
static constexpr size_t OFF_DINVA = OFF_DEGB + NN;
static constexpr size_t OFF_DINVB = OFF_DINVA + NN;
static constexpr size_t OFF_POOL  = OFF_DINVB + NN;            // [NG,512]
static constexpr size_t OFF_CNT   = OFF_POOL + (size_t)NG*512; // [NG]
static constexpr size_t OFF_WT    = OFF_CNT + NG;              // bf16x2-packed weights [256*320 u32]
static constexpr size_t BUF_TOTAL = OFF_WT + (size_t)256*320;

__device__ float g_buf[BUF_TOTAL];

// packed edge records: {gather_idx, weight_bits}; fwd at [0,NE), rev at [NE,2NE)
__device__ int2 g_ev[2 * NE];

// ---------------- int scratch ----------------
static constexpr int IB_ROWF = 0;
static constexpr int IB_ROWR = NN;
static constexpr int IB_CURF = 2*NN;   // after scatter: row end
static constexpr int IB_CURR = 3*NN;
static constexpr int IB_BSF  = 4*NN;
static constexpr int IB_BSR  = IB_BSF + 128;
static constexpr int IB_TOTAL= IB_BSR + 128;

__device__ int g_ib[IB_TOTAL];

static constexpr int NB = (NN + 1023) / 1024;

// ============================================================
// helpers
// ============================================================
__device__ __forceinline__ uint32_t pack_bf16(float lo, float hi) {
    uint32_t u;
    asm("cvt.rn.bf16x2.f32 %0, %1, %2;" : "=r"(u) : "f"(hi), "f"(lo));
    return u;
}

__device__ __forceinline__ void mma16816(float* d, const uint32_t* a, const uint32_t* b) {
    asm volatile(
        "mma.sync.aligned.m16n8k16.row.col.f32.bf16.bf16.f32 "
        "{%0,%1,%2,%3}, {%4,%5,%6,%7}, {%8,%9}, {%0,%1,%2,%3};"
        : "+f"(d[0]), "+f"(d[1]), "+f"(d[2]), "+f"(d[3])
        : "r"(a[0]), "r"(a[1]), "r"(a[2]), "r"(a[3]), "r"(b[0]), "r"(b[1]));
}

// ============================================================
// small utility kernels
// ============================================================
__global__ void k_zero(size_t off, int n) {
    int i = blockIdx.x * blockDim.x + threadIdx.x;
    if (i < n) g_buf[off + i] = 0.0f;
}

__global__ void k_deg(const int* __restrict__ src, const int* __restrict__ dst) {
    int e = blockIdx.x * blockDim.x + threadIdx.x;
    if (e >= NE) return;
    atomicAdd(&g_buf[OFF_DEGA + src[e]], 1.0f);
    atomicAdd(&g_buf[OFF_DEGB + dst[e]], 1.0f);
}

__global__ void k_dinv() {
    int n = blockIdx.x * blockDim.x + threadIdx.x;
    if (n >= NN) return;
    float a = g_buf[OFF_DEGA + n];
    float b = g_buf[OFF_DEGB + n];
    g_buf[OFF_DINVA + n] = (a > 0.0f) ? rsqrtf(a) : 0.0f;
    g_buf[OFF_DINVB + n] = (b > 0.0f) ? rsqrtf(b) : 0.0f;
}

// ============================================================
// CSR build: block sums -> scan -> row starts -> scatter
// ============================================================
__global__ void k_blocksum() {
    int tid  = threadIdx.x;
    int i    = blockIdx.x * 1024 + tid;
    int lane = tid & 31, wid = tid >> 5;
    int dF = (i < NN) ? (int)g_buf[OFF_DEGB + i] : 0;
    int dR = (i < NN) ? (int)g_buf[OFF_DEGA + i] : 0;
    #pragma unroll
    for (int o = 16; o > 0; o >>= 1) {
        dF += __shfl_down_sync(0xffffffffu, dF, o);
        dR += __shfl_down_sync(0xffffffffu, dR, o);
    }
    __shared__ int sF[32], sR[32];
    if (lane == 0) { sF[wid] = dF; sR[wid] = dR; }
    __syncthreads();
    if (wid == 0) {
        int vF = sF[lane], vR = sR[lane];
        #pragma unroll
        for (int o = 16; o > 0; o >>= 1) {
            vF += __shfl_down_sync(0xffffffffu, vF, o);
            vR += __shfl_down_sync(0xffffffffu, vR, o);
        }
        if (lane == 0) { g_ib[IB_BSF + blockIdx.x] = vF; g_ib[IB_BSR + blockIdx.x] = vR; }
    }
}

__global__ void k_scanblocks() {
    __shared__ int sF[128], sR[128];
    int tid = threadIdx.x;
    int vF = (tid < NB) ? g_ib[IB_BSF + tid] : 0;
    int vR = (tid < NB) ? g_ib[IB_BSR + tid] : 0;
    sF[tid] = vF; sR[tid] = vR;
    __syncthreads();
    for (int s = 1; s < 128; s <<= 1) {
        int aF = (tid >= s) ? sF[tid - s] : 0;
        int aR = (tid >= s) ? sR[tid - s] : 0;
        __syncthreads();
        sF[tid] += aF; sR[tid] += aR;
        __syncthreads();
    }
    if (tid < NB) {
        g_ib[IB_BSF + tid] = sF[tid] - vF;
        g_ib[IB_BSR + tid] = sR[tid] - vR;
    }
}

__global__ void k_writerow() {
    int tid = threadIdx.x;
    int i   = blockIdx.x * 1024 + tid;
    int lane = tid & 31, wid = tid >> 5;
    int dF = (i < NN) ? (int)g_buf[OFF_DEGB + i] : 0;
    int dR = (i < NN) ? (int)g_buf[OFF_DEGA + i] : 0;
    int iF = dF, iR = dR;
    #pragma unroll
    for (int o = 1; o < 32; o <<= 1) {
        int tF = __shfl_up_sync(0xffffffffu, iF, o);
        int tR = __shfl_up_sync(0xffffffffu, iR, o);
        if (lane >= o) { iF += tF; iR += tR; }
    }
    __shared__ int wsF[32], wsR[32];
    if (lane == 31) { wsF[wid] = iF; wsR[wid] = iR; }
    __syncthreads();
    if (wid == 0) {
        int vF = wsF[lane], vR = wsR[lane];
        int jF = vF, jR = vR;
        #pragma unroll
        for (int o = 1; o < 32; o <<= 1) {
            int tF = __shfl_up_sync(0xffffffffu, jF, o);
            int tR = __shfl_up_sync(0xffffffffu, jR, o);
            if (lane >= o) { jF += tF; jR += tR; }
        }
        wsF[lane] = jF - vF;
        wsR[lane] = jR - vR;
    }
    __syncthreads();
    int exF = (iF - dF) + wsF[wid] + g_ib[IB_BSF + blockIdx.x];
    int exR = (iR - dR) + wsR[wid] + g_ib[IB_BSR + blockIdx.x];
    if (i < NN) {
        g_ib[IB_ROWF + i] = exF; g_ib[IB_CURF + i] = exF;
        g_ib[IB_ROWR + i] = exR; g_ib[IB_CURR + i] = exR;
    }
}

__global__ void k_scatter(const int* __restrict__ src, const int* __restrict__ dst) {
    int e = blockIdx.x * blockDim.x + threadIdx.x;
    if (e >= NE) return;
    int s = src[e], d = dst[e];
    float dAs = g_buf[OFF_DINVA + s], dAd = g_buf[OFF_DINVA + d];
    float dBs = g_buf[OFF_DINVB + s], dBd = g_buf[OFF_DINVB + d];
    float wf = -dAs * dAd;
    float wr = -dBd * dBs;
    int pF = atomicAdd(&g_ib[IB_CURF + d], 1);
    g_ev[pF] = make_int2(s, __float_as_int(wf));
    int pR = atomicAdd(&g_ib[IB_CURR + s], 1);
    g_ev[NE + pR] = make_int2(d, __float_as_int(wr));
}

// ============================================================
// copy Tx0 slice into TxAll[:,0:F]
// ============================================================
template<int F>
__global__ void col_copy(size_t dstOff, int dstLd, int mode,
                         const float* __restrict__ ext, size_t srcOff, int srcLd) {
    constexpr int P = F / 4;
    int t = blockIdx.x * blockDim.x + threadIdx.x;
    if (t >= NN * P) return;
    int n = t / P;
    int j = (t % P) * 4;
    float4 v;
    if (mode == 1) v = *(const float4*)(ext + (size_t)n * srcLd + j);
    else           v = *(const float4*)&g_buf[srcOff + (size_t)n * srcLd + j];
    *(float4*)&g_buf[dstOff + (size_t)n * dstLd + j] = v;
}

// ============================================================
// full-width gather CSR SpMM with fused Chebyshev recursion.
// F=128: one warp per node, each edge fetched once as contiguous 512B.
// prev is read with evict-first (.cs) - dead after this read; gather via
// __ldg; out stays normal (it is the next launch's gather source).
// Simple serial edge loop (R8-proven; x4 unroll regressed at mean deg 6).
// ============================================================
template<int F>
__global__ void spmm_f(size_t inOff, size_t outOff, size_t prevOff, int hasPrev,
                       int ld, int rowBase, int curBase, int evBase) {
    constexpr int LPN = F / 4;
    int gtid = blockIdx.x * blockDim.x + threadIdx.x;
    int node = gtid / LPN;
    if (node >= NN) return;
    int sub = gtid % LPN;
    int start = g_ib[rowBase + node];
    int end   = g_ib[curBase + node];
    float ax = 0.f, ay = 0.f, az = 0.f, aw = 0.f;
    const float* inB = g_buf + inOff + sub * 4;
    const int2* evp = g_ev + evBase;
    for (int e = start; e < end; e++) {
        int2  ev = evp[e];
        float w  = __int_as_float(ev.y);
        const float4 v = __ldg((const float4*)(inB + (size_t)ev.x * ld));
        ax = fmaf(w, v.x, ax);
        ay = fmaf(w, v.y, ay);
        az = fmaf(w, v.z, az);
        aw = fmaf(w, v.w, aw);
    }
    float4 r;
    if (hasPrev) {
        const float4 p = __ldcs((const float4*)&g_buf[prevOff + (size_t)node * ld + sub * 4]);
        r.x = 2.f * ax - p.x; r.y = 2.f * ay - p.y;
        r.z = 2.f * az - p.z; r.w = 2.f * aw - p.w;
    } else {
        r.x = ax; r.y = ay; r.z = az; r.w = aw;
    }
    *(float4*)&g_buf[outOff + (size_t)node * ld + sub * 4] = r;
}

// ============================================================
// weight transpose + bf16x2 pack
// ============================================================
__global__ void k_transb(const float* __restrict__ W, int Kdim, int FOUT) {
    int K2 = Kdim / 2;
    int t = blockIdx.x * blockDim.x + threadIdx.x;
    if (t >= FOUT * K2) return;
    int n = t / K2, k2 = t % K2;
    float lo = W[(size_t)(2 * k2) * FOUT + n];
    float hi = W[(size_t)(2 * k2 + 1) * FOUT + n];
    g_buf[OFF_WT + t] = __uint_as_float(pack_bf16(lo, hi));
}

// ============================================================
// bf16 mma.sync GEMM: C[:, hc0 + n0 : +BN] = relu(A[NN,Kdim] @ WT^T + bias)
// ============================================================
template<int BN, int BK>
__global__ void __launch_bounds__(256)
gemm_bf16(size_t aOff, int lda, int Kdim,
          const float* __restrict__ bias, size_t cOff, int ldc, int hc0) {
    constexpr int BM = 128;
    constexpr int PW = BK / 2 + 4;
    constexpr int KS = BK / 16;
    constexpr int NT = BN / 32;
    constexpr int ASZ = BM * PW;
    constexpr int BSZ = BN * PW;
    constexpr int AOCT = BM * BK / 8;
    constexpr int AO_PER = (AOCT + 255) / 256;
    constexpr int BQ  = BN * BK / 8;
    constexpr int BO_PER = (BQ + 255) / 256;
    constexpr int OPR = BK / 8;

    __shared__ uint32_t sm[2 * ASZ + 2 * BSZ];
    uint32_t* As[2] = { sm, sm + ASZ };
    uint32_t* Bs[2] = { sm + 2 * ASZ, sm + 2 * ASZ + BSZ };

    int tid  = threadIdx.x;
    int wid  = tid >> 5;
    int lane = tid & 31;
    int wm   = wid >> 2;
    int wn   = wid & 3;
    int m0   = blockIdx.x * BM;
    int n0   = blockIdx.y * BN;
    int l4   = lane >> 2;
    int lq   = lane & 3;
    const int K2 = Kdim / 2;
    const uint32_t* WTu = (const uint32_t*)&g_buf[OFF_WT];

    float acc[4][NT][4];
    #pragma unroll
    for (int mt = 0; mt < 4; mt++)
        #pragma unroll
        for (int nt = 0; nt < NT; nt++)
            #pragma unroll
            for (int q = 0; q < 4; q++) acc[mt][nt][q] = 0.f;

    const int NC = Kdim / BK;

    float4 ra[AO_PER][2];
    uint4  rb[BO_PER];

    auto ldg = [&](int kc) {
        int k0 = kc * BK;
        #pragma unroll
        for (int i = 0; i < AO_PER; i++) {
            int id = tid + i * 256;
            int r = id / OPR, o = id % OPR;
            int gr = m0 + r;
            if (gr < NN) {
                ra[i][0] = *(const float4*)&g_buf[aOff + (size_t)gr * lda + k0 + o * 8];
                ra[i][1] = *(const float4*)&g_buf[aOff + (size_t)gr * lda + k0 + o * 8 + 4];
            } else {
                ra[i][0] = make_float4(0.f, 0.f, 0.f, 0.f);
                ra[i][1] = make_float4(0.f, 0.f, 0.f, 0.f);
            }
        }
        #pragma unroll
        for (int i = 0; i < BO_PER; i++) {
            int id = tid + i * 256;
            if ((BQ & 255) == 0 || id < BQ) {
                int r = id / OPR, q = id % OPR;
                rb[i] = *(const uint4*)&WTu[(size_t)(n0 + r) * K2 + kc * (BK / 2) + q * 4];
            }
        }
    };

    auto sts = [&](int st) {
        #pragma unroll
        for (int i = 0; i < AO_PER; i++) {
            int id = tid + i * 256;
            int r = id / OPR, o = id % OPR;
            uint4 u;
            u.x = pack_bf16(ra[i][0].x, ra[i][0].y);
            u.y = pack_bf16(ra[i][0].z, ra[i][0].w);
            u.z = pack_bf16(ra[i][1].x, ra[i][1].y);
            u.w = pack_bf16(ra[i][1].z, ra[i][1].w);
            *(uint4*)&As[st][r * PW + o * 4] = u;
        }
        #pragma unroll
        for (int i = 0; i < BO_PER; i++) {
            int id = tid + i * 256;
            if ((BQ & 255) == 0 || id < BQ) {
                int r = id / OPR, q = id % OPR;
                *(uint4*)&Bs[st][r * PW + q * 4] = rb[i];
            }
        }
    };

    auto compute = [&](int st) {
        const uint32_t* aB = As[st] + (wm * 64 + l4) * PW + lq;
        const uint32_t* bB = Bs[st] + (wn * (BN / 4) + l4) * PW + lq;
        #pragma unroll
        for (int ks = 0; ks < KS; ks++) {
            uint32_t af[4][4];
            #pragma unroll
            for (int mt = 0; mt < 4; mt++) {
                const uint32_t* p = aB + mt * 16 * PW + ks * 8;
                af[mt][0] = p[0];
                af[mt][1] = p[8 * PW];
                af[mt][2] = p[4];
                af[mt][3] = p[8 * PW + 4];
            }
            uint32_t bf[NT][2];
            #pragma unroll
            for (int nt = 0; nt < NT; nt++) {
                const uint32_t* q = bB + nt * 8 * PW + ks * 8;
                bf[nt][0] = q[0];
                bf[nt][1] = q[4];
            }
            #pragma unroll
            for (int mt = 0; mt < 4; mt++)
                #pragma unroll
                for (int nt = 0; nt < NT; nt++)
                    mma16816(acc[mt][nt], af[mt], bf[nt]);
        }
    };

    ldg(0);
    sts(0);
    __syncthreads();

    for (int c = 0; c < NC; c++) {
        int st = c & 1;
        bool has = (c + 1 < NC);
        if (has) ldg(c + 1);
        compute(st);
        if (has) sts(st ^ 1);
        __syncthreads();
    }

    #pragma unroll
    for (int mt = 0; mt < 4; mt++) {
        int row = m0 + wm * 64 + mt * 16 + l4;
        #pragma unroll
        for (int nt = 0; nt < NT; nt++) {
            int col = n0 + wn * (BN / 4) + nt * 8 + 2 * lq;
            float b0 = bias[col], b1 = bias[col + 1];
            if (row < NN) {
                float2 o0;
                o0.x = fmaxf(acc[mt][nt][0] + b0, 0.f);
                o0.y = fmaxf(acc[mt][nt][1] + b1, 0.f);
                *(float2*)&g_buf[cOff + (size_t)row * ldc + hc0 + col] = o0;
            }
            if (row + 8 < NN) {
                float2 o1;
                o1.x = fmaxf(acc[mt][nt][2] + b0, 0.f);
                o1.y = fmaxf(acc[mt][nt][3] + b1, 0.f);
                *(float2*)&g_buf[cOff + (size_t)(row + 8) * ldc + hc0 + col] = o1;
            }
        }
    }
}

// ============================================================
// pooling + head
// ============================================================
__global__ void k_cnt(const int* __restrict__ batch) {
    int i = blockIdx.x * blockDim.x + threadIdx.x;
    if (i >= NN) return;
    atomicAdd(&g_buf[OFF_CNT + batch[i]], 1.0f);
}

__global__ void pool_kernel(const int* __restrict__ batch) {
    constexpr int NPB = 512;
    __shared__ int sb[NPB];
    int n0  = blockIdx.x * NPB;
    int tid = threadIdx.x;
    int nmax = NN - n0; if (nmax > NPB) nmax = NPB;
    if (tid < nmax) sb[tid] = batch[n0 + tid];
    __syncthreads();
    int f = tid;
    float acc = 0.f;
    int cur = sb[0];
    for (int i = 0; i < nmax; i++) {
        int b = sb[i];
        if (b != cur) {
            atomicAdd(&g_buf[OFF_POOL + (size_t)cur * 512 + f], acc);
            acc = 0.f; cur = b;
        }
        acc += g_buf[OFF_H2 + (size_t)(n0 + i) * 512 + f];
    }
    atomicAdd(&g_buf[OFF_POOL + (size_t)cur * 512 + f], acc);
}

__global__ void head_kernel(const float* __restrict__ fcw, const float* __restrict__ fcb,
                            float* __restrict__ out) {
    int g = blockIdx.x;
    int tid = threadIdx.x;
    __shared__ float red[128][4];
    float acc[4] = {0.f, 0.f, 0.f, 0.f};
    for (int j = tid; j < 512; j += 128) {
        float p = g_buf[OFF_POOL + (size_t)g * 512 + j];
        #pragma unroll
        for (int c = 0; c < 4; c++) acc[c] = fmaf(p, fcw[j * 4 + c], acc[c]);
    }
    #pragma unroll
    for (int c = 0; c < 4; c++) red[tid][c] = acc[c];
    __syncthreads();
    for (int s = 64; s > 0; s >>= 1) {
        if (tid < s) {
            #pragma unroll
            for (int c = 0; c < 4; c++) red[tid][c] += red[tid + s][c];
        }
        __syncthreads();
    }
    if (tid == 0) {
        float ic = 1.0f / fmaxf(g_buf[OFF_CNT + g], 1.0f);
        float l[4];
        #pragma unroll
        for (int c = 0; c < 4; c++) l[c] = red[0][c] * ic + fcb[c];
        float m = fmaxf(fmaxf(l[0], l[1]), fmaxf(l[2], l[3]));
        float s = 0.f;
        #pragma unroll
        for (int c = 0; c < 4; c++) s += expf(l[c] - m);
        float ls = logf(s);
        #pragma unroll
        for (int c = 0; c < 4; c++) out[g * 4 + c] = l[c] - m - ls;
    }
}

// ============================================================
// host-side conv driver
// ============================================================
static inline int cdiv_ll(long long a, int b) { return (int)((a + b - 1) / b); }

template<int F, int FOUT>
static void run_conv(const float* extX, size_t xOff, int xLd, int xmode,
                     int rowBase, int curBase, int evBase,
                     const float* Wstack, const float* bias,
                     size_t hOff, int hLd, int hc0) {
    constexpr int LD = 5 * F;
    constexpr int LPN = F / 4;
    int spGrid = cdiv_ll((long long)NN * LPN, 256);

    col_copy<F><<<spGrid, 256>>>(OFF_TX, LD, xmode, extX, xOff, xLd);
    // full-width Chebyshev chain: T1 then T2..T4
    spmm_f<F><<<spGrid, 256>>>(OFF_TX, OFF_TX + F, 0, 0, LD,
                               rowBase, curBase, evBase);
    for (int k = 2; k < 5; k++) {
        spmm_f<F><<<spGrid, 256>>>(OFF_TX + (size_t)(k - 1) * F,
                                   OFF_TX + (size_t)k * F,
                                   OFF_TX + (size_t)(k - 2) * F, 1, LD,
                                   rowBase, curBase, evBase);
    }
    k_transb<<<cdiv_ll(FOUT * (LD / 2), 256), 256>>>(Wstack, LD, FOUT);
    if constexpr (FOUT == 64) {
        dim3 grid((NN + 127) / 128, 1);
        gemm_bf16<64, 16><<<grid, 256>>>(OFF_TX, LD, LD, bias, hOff, hLd, hc0);
    } else {
        dim3 grid((NN + 127) / 128, FOUT / 128);
        gemm_bf16<128, 32><<<grid, 256>>>(OFF_TX, LD, LD, bias, hOff, hLd, hc0);
    }
}

extern "C" void kernel_launch(void* const* d_in, const int* in_sizes, int n_in,
                              void* d_out, int out_size) {
    const float* x     = (const float*)d_in[0];
    const int*   ei    = (const int*)d_in[1];
    const int*   batch = (const int*)d_in[2];
    const float* W11   = (const float*)d_in[3];
    const float* b11   = (const float*)d_in[4];
    const float* W12   = (const float*)d_in[5];
    const float* b12   = (const float*)d_in[6];
    const float* W21   = (const float*)d_in[7];
    const float* b21   = (const float*)d_in[8];
    const float* W22   = (const float*)d_in[9];
    const float* b22   = (const float*)d_in[10];
    const float* fcw   = (const float*)d_in[11];
    const float* fcb   = (const float*)d_in[12];
    float* out = (float*)d_out;

    const int* src = ei;
    const int* dst = ei + NE;

    k_zero<<<cdiv_ll(2 * NN, 256), 256>>>(OFF_DEGA, 2 * NN);
    k_zero<<<cdiv_ll(NG * 512 + NG, 256), 256>>>(OFF_POOL, NG * 512 + NG);

    k_deg<<<cdiv_ll(NE, 256), 256>>>(src, dst);
    k_dinv<<<cdiv_ll(NN, 256), 256>>>();

    k_blocksum<<<NB, 1024>>>();
    k_scanblocks<<<1, 128>>>();
    k_writerow<<<NB, 1024>>>();
    k_scatter<<<cdiv_ll(NE, 256), 256>>>(src, dst);

    run_conv<16, 64>(x, 0, 16, 1, IB_ROWF, IB_CURF, 0,
                     W11, b11, OFF_H1, 128, 0);
    run_conv<16, 64>(x, 0, 16, 1, IB_ROWR, IB_CURR, NE,
                     W12, b12, OFF_H1, 128, 64);

    run_conv<128, 256>(nullptr, OFF_H1, 128, 2, IB_ROWF, IB_CURF, 0,
                       W21, b21, OFF_H2, 512, 0);
    run_conv<128, 256>(nullptr, OFF_H1, 128, 2, IB_ROWR, IB_CURR, NE,
                       W22, b22, OFF_H2, 512, 256);

    k_cnt<<<cdiv_ll(NN, 256), 256>>>(batch);
    pool_kernel<<<(NN + 511) / 512, 512>>>(batch);
    head_kernel<<<NG, 128>>>(fcw, fcb, out);
}